// round 15
// baseline (speedup 1.0000x reference)
#include <cuda_runtime.h>
#include <cuda_fp16.h>
#include <math.h>
#include <stdint.h>

// Scratch: Q1 ping-pong in both layouts. [B,S,S], B=4,S=160 -> 102400
#define MAXQ 102400
#define MAXR 1024
#define MAXE 16384000              // B*S^3 = 4*160^3
__device__ __align__(16) float g_q1 [2][MAXQ];   // Q1[b,m,h]
__device__ __align__(16) float g_q1T[2][MAXQ];   // Q1[b,h,m]
__device__ int   g_excl[MAXQ];     // per (b,h): excluded t list (mask[b,t,h]==0 || t==h)
__device__ int   g_ecnt[MAXR];     // per (b,h): list length
// fp16 copies of the score tensors (written by iter0, read by iters 2/3)
__device__ __align__(16) __half g_hss[MAXE];
__device__ __align__(16) __half g_hsc[MAXE];
__device__ __align__(16) __half g_hsg[MAXE];

// Pre-pass: build per-(b,h) exclusion list.
__global__ void excl_build_kernel(const int* __restrict__ mask, int S)
{
    __shared__ int cnt;
    int t = threadIdx.x;
    int h = blockIdx.x % S;
    int b = blockIdx.x / S;
    int row = b * S + h;
    if (t == 0) cnt = 0;
    __syncthreads();
    if (t < S) {
        bool ex = (mask[(b * S + t) * S + h] == 0) || (t == h);
        if (ex) {
            int slot = atomicAdd(&cnt, 1);
            g_excl[row * S + slot] = t;
        }
    }
    __syncthreads();
    if (t == 0) g_ecnt[row] = cnt;
}

// ============================================================================
// Iter 1 (Q1 = 0.5), fused fp32->fp16 conversion. EXACT R13 codegen (single acc).
// ============================================================================
template<int SS>
__global__ void __launch_bounds__(256, 4)
mfvi_iter0_conv(const float* __restrict__ se,
                const float* __restrict__ ss,
                const float* __restrict__ sc,
                const float* __restrict__ sg,
                const int* __restrict__ mask,
                int outbuf)
{
    constexpr int HT = 32;
    constexpr int NTILE = SS / HT;
    constexpr int FV = SS >> 2;
    constexpr int KK = FV / 8;     // 5

    int blk = blockIdx.x;
    int htile = blk % NTILE;
    int m     = (blk / NTILE) % SS;
    int b     = blk / (NTILE * SS);
    int warp = threadIdx.x >> 5, lane = threadIdx.x & 31;
    int g = lane >> 3, li = lane & 7;
    int h = htile * HT + warp * 4 + g;

    const long sbase = (((long)(b * SS + m)) * SS + h) * SS;
    const float4* p_ss = (const float4*)(ss + sbase);
    const float4* p_sc = (const float4*)(sc + sbase);
    const float4* p_sg = (const float4*)(sg + sbase);
    uint2* w_ss = (uint2*)(g_hss + sbase);
    uint2* w_sc = (uint2*)(g_hsc + sbase);
    uint2* w_sg = (uint2*)(g_hsg + sbase);

    float acc = 0.f;
    #pragma unroll
    for (int k = 0; k < KK; k++) {
        int v = li + 8 * k;
        float4 vss = __ldcs(p_ss + v);
        float4 vsc = __ldcs(p_sc + v);
        float4 vsg = __ldcs(p_sg + v);
        #pragma unroll
        for (int j = 0; j < 4; j++)
            acc += (&vss.x)[j] + (&vsc.x)[j] + (&vsg.x)[j];
        __half2 a0 = __floats2half2_rn(vss.x, vss.y), a1 = __floats2half2_rn(vss.z, vss.w);
        __half2 b0 = __floats2half2_rn(vsc.x, vsc.y), b1 = __floats2half2_rn(vsc.z, vsc.w);
        __half2 c0 = __floats2half2_rn(vsg.x, vsg.y), c1 = __floats2half2_rn(vsg.z, vsg.w);
        uint2 u;
        u.x = *(unsigned*)&a0; u.y = *(unsigned*)&a1; __stcs(w_ss + v, u);
        u.x = *(unsigned*)&b0; u.y = *(unsigned*)&b1; __stcs(w_sc + v, u);
        u.x = *(unsigned*)&c0; u.y = *(unsigned*)&c1; __stcs(w_sg + v, u);
    }
    acc += __shfl_down_sync(0xffffffffu, acc, 4, 8);
    acc += __shfl_down_sync(0xffffffffu, acc, 2, 8);
    acc += __shfl_down_sync(0xffffffffu, acc, 1, 8);

    if (li == 0) {
        int idx = (b * SS + m) * SS + h;
        float f = 0.f;
        if (mask[idx] != 0) {
            acc *= 0.5f;
            int row = b * SS + h;
            int cnt = g_ecnt[row];
            for (int i = 0; i < cnt; i++) {
                int t = g_excl[row * SS + i];
                acc -= 0.5f * (ss[sbase + t] + sc[sbase + t] + sg[sbase + t]);
            }
            if (m != h)
                acc -= 0.5f * (ss[sbase + m] + sc[sbase + m] + sg[sbase + m]);
            f = acc;
        }
        float q = se[idx] + f;
        float q1v = 1.f / (1.f + expf(-q));
        g_q1 [outbuf][idx] = q1v;
        g_q1T[outbuf][(b * SS + h) * SS + m] = q1v;
    }
}

// unpack 8 halves (uint4) -> 8 floats
__device__ __forceinline__ void h8f(const uint4& u, float* f) {
    float2 t;
    t = __half22float2(*(const __half2*)&u.x); f[0] = t.x; f[1] = t.y;
    t = __half22float2(*(const __half2*)&u.y); f[2] = t.x; f[3] = t.y;
    t = __half22float2(*(const __half2*)&u.z); f[4] = t.x; f[5] = t.y;
    t = __half22float2(*(const __half2*)&u.w); f[6] = t.x; f[7] = t.y;
}

// ============================================================================
// Iters 2/3: fp16 score streams + smem-staged qa rows (coalesced block copy).
// 128 threads, 4-lane groups, 32 h-rows/block, 3 accumulators.
// ============================================================================
template<int FINAL, int SS>
__global__ void __launch_bounds__(128)
mfvi_iter_h(const float* __restrict__ se,
            const int* __restrict__ mask,
            float* __restrict__ out,
            int parity)
{
    constexpr int HT = 32;
    constexpr int NTILE = SS / HT;
    constexpr int FV = SS >> 2;    // 40 float4 per row
    constexpr int CH = SS / 8;     // 20 uint4(half8) chunks per row
    constexpr int KK = CH / 4;     // 5 chunks per 4-lane group lane

    int blk = blockIdx.x;
    int htile = blk % NTILE;
    int m     = (blk / NTILE) % SS;
    int b     = blk / (NTILE * SS);
    int tid = threadIdx.x;
    int w = tid >> 5, lane = tid & 31;
    int g2 = lane >> 2, li4 = lane & 3;
    int rt = w * 8 + g2;
    int h = htile * HT + rt;

    extern __shared__ float smbuf[];
    float* sm_row = smbuf;             // Q1[b,m,t]                [SS]
    float* sm_col = smbuf + SS;        // Q1[b,t,m]                [SS]
    float* sm_qa  = smbuf + 2 * SS;    // q1T rows for 32 h-rows   [HT*SS]

    const float* __restrict__ q1_in  = g_q1 [parity & 1];
    const float* __restrict__ q1T_in = g_q1T[parity & 1];

    {
        const float4* r4 = (const float4*)(q1_in  + (b * SS + m) * SS);
        const float4* c4 = (const float4*)(q1T_in + (b * SS + m) * SS);
        for (int i = tid; i < 2 * FV; i += 128) {
            if (i < FV) ((float4*)sm_row)[i] = r4[i];
            else        ((float4*)sm_col)[i - FV] = c4[i - FV];
        }
        // stage the block's 32 contiguous qa rows (20 KB, fully coalesced)
        const float4* qa4 = (const float4*)(q1T_in + ((long)(b * SS + htile * HT)) * SS);
        float4* sqa4 = (float4*)sm_qa;
        #pragma unroll 2
        for (int i = tid; i < HT * FV; i += 128)
            sqa4[i] = __ldg(qa4 + i);
        __syncthreads();
    }

    const long sbase = (((long)(b * SS + m)) * SS + h) * SS;
    const uint4* pss = (const uint4*)(g_hss + sbase);
    const uint4* psc = (const uint4*)(g_hsc + sbase);
    const uint4* psg = (const uint4*)(g_hsg + sbase);
    const float4* pqa = (const float4*)(sm_qa + rt * SS);
    const float4* srow = (const float4*)sm_row;
    const float4* scol = (const float4*)sm_col;

    float accA = 0.f, accB = 0.f, accC = 0.f;   // per-tensor accumulators
    #pragma unroll
    for (int k = 0; k < KK; k++) {
        int c = li4 + 4 * k;
        uint4 ua = __ldcs(pss + c);
        uint4 ub = __ldcs(psc + c);
        uint4 uc = __ldcs(psg + c);
        float4 q0 = pqa[2 * c], q1v = pqa[2 * c + 1];
        float4 r0 = srow[2 * c], r1 = srow[2 * c + 1];
        float4 c0 = scol[2 * c], c1 = scol[2 * c + 1];
        float fa[8], fb[8], fc[8];
        h8f(ua, fa); h8f(ub, fb); h8f(uc, fc);
        float qv[8] = {q0.x, q0.y, q0.z, q0.w, q1v.x, q1v.y, q1v.z, q1v.w};
        float rv[8] = {r0.x, r0.y, r0.z, r0.w, r1.x, r1.y, r1.z, r1.w};
        float cv[8] = {c0.x, c0.y, c0.z, c0.w, c1.x, c1.y, c1.z, c1.w};
        #pragma unroll
        for (int j = 0; j < 8; j++) {
            accA += fa[j] * qv[j];
            accB += fb[j] * rv[j];
            accC += fc[j] * cv[j];
        }
    }

    float acc = (accA + accB) + accC;
    acc += __shfl_down_sync(0xffffffffu, acc, 2, 4);
    acc += __shfl_down_sync(0xffffffffu, acc, 1, 4);

    if (li4 == 0) {
        int idx = (b * SS + m) * SS + h;
        float f = 0.f;
        if (mask[idx] != 0) {
            const float* qa_r = sm_qa + rt * SS;
            int row = b * SS + h;
            int cnt = g_ecnt[row];
            for (int i = 0; i < cnt; i++) {
                int t = g_excl[row * SS + i];
                acc -= __half2float(g_hss[sbase + t]) * qa_r[t]
                     + __half2float(g_hsc[sbase + t]) * sm_row[t]
                     + __half2float(g_hsg[sbase + t]) * sm_col[t];
            }
            if (m != h)
                acc -= __half2float(g_hss[sbase + m]) * qa_r[m]
                     + __half2float(g_hsc[sbase + m]) * sm_row[m]
                     + __half2float(g_hsg[sbase + m]) * sm_col[m];
            f = acc;
        }
        float q = se[idx] + f;
        if (FINAL) {
            out[(long)idx * 2 + 0] = 1.f / (1.f + expf(q));
            out[(long)idx * 2 + 1] = 1.f / (1.f + expf(-q));
        } else {
            float q1v = 1.f / (1.f + expf(-q));
            int ob = (parity ^ 1) & 1;
            g_q1 [ob][idx] = q1v;
            g_q1T[ob][(b * SS + h) * SS + m] = q1v;
        }
    }
}

// ============================================================================
// Generic fp32 fallback for S != 160
// ============================================================================
__global__ void __launch_bounds__(256, 4)
mfvi_iter0_gen(const float* __restrict__ se,
               const float* __restrict__ ss,
               const float* __restrict__ sc,
               const float* __restrict__ sg,
               const int* __restrict__ mask,
               int S, int outbuf)
{
    const int HT = 32;
    int ntile = (S + HT - 1) / HT;
    int blk = blockIdx.x;
    int htile = blk % ntile;
    int m     = (blk / ntile) % S;
    int b     = blk / (ntile * S);
    int warp = threadIdx.x >> 5, lane = threadIdx.x & 31;
    int g = lane >> 3, li = lane & 7;
    int h = htile * HT + warp * 4 + g;
    bool valid = (h < S);
    const long sbase = (((long)(b * S + m)) * S + h) * S;

    float acc = 0.f;
    if (valid) {
        for (int t = li; t < S; t += 8)
            acc += ss[sbase + t] + sc[sbase + t] + sg[sbase + t];
    }
    acc += __shfl_down_sync(0xffffffffu, acc, 4, 8);
    acc += __shfl_down_sync(0xffffffffu, acc, 2, 8);
    acc += __shfl_down_sync(0xffffffffu, acc, 1, 8);
    if (li == 0 && valid) {
        int idx = (b * S + m) * S + h;
        float f = 0.f;
        if (mask[idx] != 0) {
            acc *= 0.5f;
            int row = b * S + h;
            int cnt = g_ecnt[row];
            for (int i = 0; i < cnt; i++) {
                int t = g_excl[row * S + i];
                acc -= 0.5f * (ss[sbase + t] + sc[sbase + t] + sg[sbase + t]);
            }
            if (m != h)
                acc -= 0.5f * (ss[sbase + m] + sc[sbase + m] + sg[sbase + m]);
            f = acc;
        }
        float q = se[idx] + f;
        float q1v = 1.f / (1.f + expf(-q));
        g_q1 [outbuf][idx] = q1v;
        g_q1T[outbuf][(b * S + h) * S + m] = q1v;
    }
}

template<int FINAL>
__global__ void __launch_bounds__(256, 4)
mfvi_fallback(const float* __restrict__ se,
              const float* __restrict__ ss,
              const float* __restrict__ sc,
              const float* __restrict__ sg,
              const int* __restrict__ mask,
              float* __restrict__ out,
              int S, int parity)
{
    const int HT = 32;
    int ntile = (S + HT - 1) / HT;
    int blk = blockIdx.x;
    int htile = blk % ntile;
    int m     = (blk / ntile) % S;
    int b     = blk / (ntile * S);
    int warp = threadIdx.x >> 5, lane = threadIdx.x & 31;
    int g = lane >> 3, li = lane & 7;
    int h = htile * HT + warp * 4 + g;

    extern __shared__ float smbuf[];
    float* sm_row = smbuf;
    float* sm_col = smbuf + S;
    const float* __restrict__ q1_in  = g_q1 [parity & 1];
    const float* __restrict__ q1T_in = g_q1T[parity & 1];
    for (int i = threadIdx.x; i < 2 * S; i += blockDim.x) {
        if (i < S) sm_row[i] = q1_in[(b * S + m) * S + i];
        else       sm_col[i - S] = q1T_in[(b * S + m) * S + (i - S)];
    }
    __syncthreads();

    bool valid = (h < S);
    const long sbase = (((long)(b * S + m)) * S + h) * S;
    const long hbase = ((long)(b * S + h)) * S;
    float acc = 0.f;
    if (valid) {
        for (int t = li; t < S; t += 8)
            acc += ss[sbase + t] * q1T_in[hbase + t]
                 + sc[sbase + t] * sm_row[t]
                 + sg[sbase + t] * sm_col[t];
    }
    acc += __shfl_down_sync(0xffffffffu, acc, 4, 8);
    acc += __shfl_down_sync(0xffffffffu, acc, 2, 8);
    acc += __shfl_down_sync(0xffffffffu, acc, 1, 8);
    if (li == 0 && valid) {
        int idx = (b * S + m) * S + h;
        float f = 0.f;
        if (mask[idx] != 0) {
            int row = b * S + h;
            int cnt = g_ecnt[row];
            for (int i = 0; i < cnt; i++) {
                int t = g_excl[row * S + i];
                acc -= ss[sbase + t] * q1T_in[hbase + t]
                     + sc[sbase + t] * sm_row[t]
                     + sg[sbase + t] * sm_col[t];
            }
            if (m != h)
                acc -= ss[sbase + m] * q1T_in[hbase + m]
                     + sc[sbase + m] * sm_row[m]
                     + sg[sbase + m] * sm_col[m];
            f = acc;
        }
        float q = se[idx] + f;
        if (FINAL) {
            out[(long)idx * 2 + 0] = 1.f / (1.f + expf(q));
            out[(long)idx * 2 + 1] = 1.f / (1.f + expf(-q));
        } else {
            float q1v = 1.f / (1.f + expf(-q));
            int ob = (parity ^ 1) & 1;
            g_q1 [ob][idx] = q1v;
            g_q1T[ob][(b * S + h) * S + m] = q1v;
        }
    }
}

extern "C" void kernel_launch(void* const* d_in, const int* in_sizes, int n_in,
                              void* d_out, int out_size)
{
    const float* se = (const float*)d_in[0];
    const float* ss = (const float*)d_in[1];
    const float* sc = (const float*)d_in[2];
    const float* sg = (const float*)d_in[3];
    const int* mask = (const int*)d_in[4];
    float* out = (float*)d_out;

    int BSS = in_sizes[0];                  // B*S*S
    int S = in_sizes[1] / BSS;              // (B*S^3)/(B*S^2)
    int B = BSS / (S * S);

    excl_build_kernel<<<B * S, (S + 31) & ~31>>>(mask, S);

    int ntile = (S + 31) / 32;
    dim3 grid(B * S * ntile);

    if (S == 160) {
        size_t smemh = (2 * (size_t)160 + 32 * (size_t)160) * sizeof(float);  // 21,760 B
        // iter 1: fp32 sum (Q1=0.5) + fp16 conversion of scores -> buf 0
        mfvi_iter0_conv<160><<<grid, 256>>>(se, ss, sc, sg, mask, 0);
        // iter 2: fp16 streams, read buf 0, write buf 1
        mfvi_iter_h<0, 160><<<grid, 128, smemh>>>(se, mask, out, 0);
        // iter 3: fp16 streams, read buf 1, write output
        mfvi_iter_h<1, 160><<<grid, 128, smemh>>>(se, mask, out, 1);
    } else {
        size_t smem = 2 * (size_t)S * sizeof(float);
        mfvi_iter0_gen<<<grid, 256>>>(se, ss, sc, sg, mask, S, 0);
        mfvi_fallback<0><<<grid, 256, smem>>>(se, ss, sc, sg, mask, out, S, 0);
        mfvi_fallback<1><<<grid, 256, smem>>>(se, ss, sc, sg, mask, out, S, 1);
    }
}

// round 16
// speedup vs baseline: 1.4023x; 1.4023x over previous
#include <cuda_runtime.h>
#include <cuda_fp16.h>
#include <math.h>
#include <stdint.h>

// Scratch: Q1 ping-pong in both layouts. [B,S,S], B=4,S=160 -> 102400
#define MAXQ 102400
#define MAXR 1024
#define MAXE 16384000              // B*S^3 = 4*160^3
__device__ __align__(16) float g_q1 [2][MAXQ];   // Q1[b,m,h]
__device__ __align__(16) float g_q1T[2][MAXQ];   // Q1[b,h,m]
__device__ int   g_excl[MAXQ];     // per (b,h): excluded t list (mask[b,t,h]==0 || t==h)
__device__ int   g_ecnt[MAXR];     // per (b,h): list length
// fp16 copies of the score tensors (written by iter0, read by iters 2/3)
__device__ __align__(16) __half g_hss[MAXE];
__device__ __align__(16) __half g_hsc[MAXE];
__device__ __align__(16) __half g_hsg[MAXE];

// Pre-pass: build per-(b,h) exclusion list.
__global__ void excl_build_kernel(const int* __restrict__ mask, int S)
{
    __shared__ int cnt;
    int t = threadIdx.x;
    int h = blockIdx.x % S;
    int b = blockIdx.x / S;
    int row = b * S + h;
    if (t == 0) cnt = 0;
    __syncthreads();
    if (t < S) {
        bool ex = (mask[(b * S + t) * S + h] == 0) || (t == h);
        if (ex) {
            int slot = atomicAdd(&cnt, 1);
            g_excl[row * S + slot] = t;
        }
    }
    __syncthreads();
    if (t == 0) g_ecnt[row] = cnt;
}

// ============================================================================
// Iter 1 (Q1 = 0.5), fused fp32->fp16 conversion. EXACT R13 codegen (single acc).
// ============================================================================
template<int SS>
__global__ void __launch_bounds__(256, 4)
mfvi_iter0_conv(const float* __restrict__ se,
                const float* __restrict__ ss,
                const float* __restrict__ sc,
                const float* __restrict__ sg,
                const int* __restrict__ mask,
                int outbuf)
{
    constexpr int HT = 32;
    constexpr int NTILE = SS / HT;
    constexpr int FV = SS >> 2;
    constexpr int KK = FV / 8;     // 5

    int blk = blockIdx.x;
    int htile = blk % NTILE;
    int m     = (blk / NTILE) % SS;
    int b     = blk / (NTILE * SS);
    int warp = threadIdx.x >> 5, lane = threadIdx.x & 31;
    int g = lane >> 3, li = lane & 7;
    int h = htile * HT + warp * 4 + g;

    const long sbase = (((long)(b * SS + m)) * SS + h) * SS;
    const float4* p_ss = (const float4*)(ss + sbase);
    const float4* p_sc = (const float4*)(sc + sbase);
    const float4* p_sg = (const float4*)(sg + sbase);
    uint2* w_ss = (uint2*)(g_hss + sbase);
    uint2* w_sc = (uint2*)(g_hsc + sbase);
    uint2* w_sg = (uint2*)(g_hsg + sbase);

    float acc = 0.f;
    #pragma unroll
    for (int k = 0; k < KK; k++) {
        int v = li + 8 * k;
        float4 vss = __ldcs(p_ss + v);
        float4 vsc = __ldcs(p_sc + v);
        float4 vsg = __ldcs(p_sg + v);
        #pragma unroll
        for (int j = 0; j < 4; j++)
            acc += (&vss.x)[j] + (&vsc.x)[j] + (&vsg.x)[j];
        __half2 a0 = __floats2half2_rn(vss.x, vss.y), a1 = __floats2half2_rn(vss.z, vss.w);
        __half2 b0 = __floats2half2_rn(vsc.x, vsc.y), b1 = __floats2half2_rn(vsc.z, vsc.w);
        __half2 c0 = __floats2half2_rn(vsg.x, vsg.y), c1 = __floats2half2_rn(vsg.z, vsg.w);
        uint2 u;
        u.x = *(unsigned*)&a0; u.y = *(unsigned*)&a1; __stcs(w_ss + v, u);
        u.x = *(unsigned*)&b0; u.y = *(unsigned*)&b1; __stcs(w_sc + v, u);
        u.x = *(unsigned*)&c0; u.y = *(unsigned*)&c1; __stcs(w_sg + v, u);
    }
    acc += __shfl_down_sync(0xffffffffu, acc, 4, 8);
    acc += __shfl_down_sync(0xffffffffu, acc, 2, 8);
    acc += __shfl_down_sync(0xffffffffu, acc, 1, 8);

    if (li == 0) {
        int idx = (b * SS + m) * SS + h;
        float f = 0.f;
        if (mask[idx] != 0) {
            acc *= 0.5f;
            int row = b * SS + h;
            int cnt = g_ecnt[row];
            for (int i = 0; i < cnt; i++) {
                int t = g_excl[row * SS + i];
                acc -= 0.5f * (ss[sbase + t] + sc[sbase + t] + sg[sbase + t]);
            }
            if (m != h)
                acc -= 0.5f * (ss[sbase + m] + sc[sbase + m] + sg[sbase + m]);
            f = acc;
        }
        float q = se[idx] + f;
        float q1v = 1.f / (1.f + expf(-q));
        g_q1 [outbuf][idx] = q1v;
        g_q1T[outbuf][(b * SS + h) * SS + m] = q1v;
    }
}

// unpack 8 halves (uint4) -> 8 floats
__device__ __forceinline__ void h8f(const uint4& u, float* f) {
    float2 t;
    t = __half22float2(*(const __half2*)&u.x); f[0] = t.x; f[1] = t.y;
    t = __half22float2(*(const __half2*)&u.y); f[2] = t.x; f[3] = t.y;
    t = __half22float2(*(const __half2*)&u.z); f[4] = t.x; f[5] = t.y;
    t = __half22float2(*(const __half2*)&u.w); f[6] = t.x; f[7] = t.y;
}

// ============================================================================
// Iters 2/3: fp16 score streams, qa direct from L2 (NO staging — R14 config).
// 128 threads, 4-lane groups, 32 h-rows/block, 3 accumulators.
// ============================================================================
template<int FINAL, int SS>
__global__ void __launch_bounds__(128)
mfvi_iter_h(const float* __restrict__ se,
            const int* __restrict__ mask,
            float* __restrict__ out,
            int parity)
{
    constexpr int HT = 32;
    constexpr int NTILE = SS / HT;
    constexpr int FV = SS >> 2;    // 40 float4 per row
    constexpr int CH = SS / 8;     // 20 uint4(half8) chunks per row
    constexpr int KK = CH / 4;     // 5 chunks per 4-lane group lane

    int blk = blockIdx.x;
    int htile = blk % NTILE;
    int m     = (blk / NTILE) % SS;
    int b     = blk / (NTILE * SS);
    int tid = threadIdx.x;
    int w = tid >> 5, lane = tid & 31;
    int g2 = lane >> 2, li4 = lane & 3;
    int rt = w * 8 + g2;
    int h = htile * HT + rt;

    extern __shared__ float smbuf[];
    float* sm_row = smbuf;        // Q1[b,m,t]
    float* sm_col = smbuf + SS;   // Q1[b,t,m]

    const float* __restrict__ q1_in  = g_q1 [parity & 1];
    const float* __restrict__ q1T_in = g_q1T[parity & 1];

    {
        const float4* r4 = (const float4*)(q1_in  + (b * SS + m) * SS);
        const float4* c4 = (const float4*)(q1T_in + (b * SS + m) * SS);
        for (int i = tid; i < 2 * FV; i += 128) {
            if (i < FV) ((float4*)sm_row)[i] = r4[i];
            else        ((float4*)sm_col)[i - FV] = c4[i - FV];
        }
        __syncthreads();
    }

    const long sbase = (((long)(b * SS + m)) * SS + h) * SS;
    const long hbase = ((long)(b * SS + h)) * SS;
    const uint4* pss = (const uint4*)(g_hss + sbase);
    const uint4* psc = (const uint4*)(g_hsc + sbase);
    const uint4* psg = (const uint4*)(g_hsg + sbase);
    const float4* pqa = (const float4*)(q1T_in + hbase);
    const float4* srow = (const float4*)sm_row;
    const float4* scol = (const float4*)sm_col;

    float accA = 0.f, accB = 0.f, accC = 0.f;   // per-tensor accumulators
    #pragma unroll
    for (int k = 0; k < KK; k++) {
        int c = li4 + 4 * k;
        uint4 ua = __ldcs(pss + c);
        uint4 ub = __ldcs(psc + c);
        uint4 uc = __ldcs(psg + c);
        float4 q0 = __ldg(pqa + 2 * c), q1v = __ldg(pqa + 2 * c + 1);
        float4 r0 = srow[2 * c], r1 = srow[2 * c + 1];
        float4 c0 = scol[2 * c], c1 = scol[2 * c + 1];
        float fa[8], fb[8], fc[8];
        h8f(ua, fa); h8f(ub, fb); h8f(uc, fc);
        float qv[8] = {q0.x, q0.y, q0.z, q0.w, q1v.x, q1v.y, q1v.z, q1v.w};
        float rv[8] = {r0.x, r0.y, r0.z, r0.w, r1.x, r1.y, r1.z, r1.w};
        float cv[8] = {c0.x, c0.y, c0.z, c0.w, c1.x, c1.y, c1.z, c1.w};
        #pragma unroll
        for (int j = 0; j < 8; j++) {
            accA += fa[j] * qv[j];
            accB += fb[j] * rv[j];
            accC += fc[j] * cv[j];
        }
    }

    float acc = (accA + accB) + accC;
    acc += __shfl_down_sync(0xffffffffu, acc, 2, 4);
    acc += __shfl_down_sync(0xffffffffu, acc, 1, 4);

    if (li4 == 0) {
        int idx = (b * SS + m) * SS + h;
        float f = 0.f;
        if (mask[idx] != 0) {
            int row = b * SS + h;
            int cnt = g_ecnt[row];
            for (int i = 0; i < cnt; i++) {
                int t = g_excl[row * SS + i];
                acc -= __half2float(g_hss[sbase + t]) * q1T_in[hbase + t]
                     + __half2float(g_hsc[sbase + t]) * sm_row[t]
                     + __half2float(g_hsg[sbase + t]) * sm_col[t];
            }
            if (m != h)
                acc -= __half2float(g_hss[sbase + m]) * q1T_in[hbase + m]
                     + __half2float(g_hsc[sbase + m]) * sm_row[m]
                     + __half2float(g_hsg[sbase + m]) * sm_col[m];
            f = acc;
        }
        float q = se[idx] + f;
        if (FINAL) {
            out[(long)idx * 2 + 0] = 1.f / (1.f + expf(q));
            out[(long)idx * 2 + 1] = 1.f / (1.f + expf(-q));
        } else {
            float q1v = 1.f / (1.f + expf(-q));
            int ob = (parity ^ 1) & 1;
            g_q1 [ob][idx] = q1v;
            g_q1T[ob][(b * SS + h) * SS + m] = q1v;
        }
    }
}

// ============================================================================
// Generic fp32 fallback for S != 160
// ============================================================================
__global__ void __launch_bounds__(256, 4)
mfvi_iter0_gen(const float* __restrict__ se,
               const float* __restrict__ ss,
               const float* __restrict__ sc,
               const float* __restrict__ sg,
               const int* __restrict__ mask,
               int S, int outbuf)
{
    const int HT = 32;
    int ntile = (S + HT - 1) / HT;
    int blk = blockIdx.x;
    int htile = blk % ntile;
    int m     = (blk / ntile) % S;
    int b     = blk / (ntile * S);
    int warp = threadIdx.x >> 5, lane = threadIdx.x & 31;
    int g = lane >> 3, li = lane & 7;
    int h = htile * HT + warp * 4 + g;
    bool valid = (h < S);
    const long sbase = (((long)(b * S + m)) * S + h) * S;

    float acc = 0.f;
    if (valid) {
        for (int t = li; t < S; t += 8)
            acc += ss[sbase + t] + sc[sbase + t] + sg[sbase + t];
    }
    acc += __shfl_down_sync(0xffffffffu, acc, 4, 8);
    acc += __shfl_down_sync(0xffffffffu, acc, 2, 8);
    acc += __shfl_down_sync(0xffffffffu, acc, 1, 8);
    if (li == 0 && valid) {
        int idx = (b * S + m) * S + h;
        float f = 0.f;
        if (mask[idx] != 0) {
            acc *= 0.5f;
            int row = b * S + h;
            int cnt = g_ecnt[row];
            for (int i = 0; i < cnt; i++) {
                int t = g_excl[row * S + i];
                acc -= 0.5f * (ss[sbase + t] + sc[sbase + t] + sg[sbase + t]);
            }
            if (m != h)
                acc -= 0.5f * (ss[sbase + m] + sc[sbase + m] + sg[sbase + m]);
            f = acc;
        }
        float q = se[idx] + f;
        float q1v = 1.f / (1.f + expf(-q));
        g_q1 [outbuf][idx] = q1v;
        g_q1T[outbuf][(b * S + h) * S + m] = q1v;
    }
}

template<int FINAL>
__global__ void __launch_bounds__(256, 4)
mfvi_fallback(const float* __restrict__ se,
              const float* __restrict__ ss,
              const float* __restrict__ sc,
              const float* __restrict__ sg,
              const int* __restrict__ mask,
              float* __restrict__ out,
              int S, int parity)
{
    const int HT = 32;
    int ntile = (S + HT - 1) / HT;
    int blk = blockIdx.x;
    int htile = blk % ntile;
    int m     = (blk / ntile) % S;
    int b     = blk / (ntile * S);
    int warp = threadIdx.x >> 5, lane = threadIdx.x & 31;
    int g = lane >> 3, li = lane & 7;
    int h = htile * HT + warp * 4 + g;

    extern __shared__ float smbuf[];
    float* sm_row = smbuf;
    float* sm_col = smbuf + S;
    const float* __restrict__ q1_in  = g_q1 [parity & 1];
    const float* __restrict__ q1T_in = g_q1T[parity & 1];
    for (int i = threadIdx.x; i < 2 * S; i += blockDim.x) {
        if (i < S) sm_row[i] = q1_in[(b * S + m) * S + i];
        else       sm_col[i - S] = q1T_in[(b * S + m) * S + (i - S)];
    }
    __syncthreads();

    bool valid = (h < S);
    const long sbase = (((long)(b * S + m)) * S + h) * S;
    const long hbase = ((long)(b * S + h)) * S;
    float acc = 0.f;
    if (valid) {
        for (int t = li; t < S; t += 8)
            acc += ss[sbase + t] * q1T_in[hbase + t]
                 + sc[sbase + t] * sm_row[t]
                 + sg[sbase + t] * sm_col[t];
    }
    acc += __shfl_down_sync(0xffffffffu, acc, 4, 8);
    acc += __shfl_down_sync(0xffffffffu, acc, 2, 8);
    acc += __shfl_down_sync(0xffffffffu, acc, 1, 8);
    if (li == 0 && valid) {
        int idx = (b * S + m) * S + h;
        float f = 0.f;
        if (mask[idx] != 0) {
            int row = b * S + h;
            int cnt = g_ecnt[row];
            for (int i = 0; i < cnt; i++) {
                int t = g_excl[row * S + i];
                acc -= ss[sbase + t] * q1T_in[hbase + t]
                     + sc[sbase + t] * sm_row[t]
                     + sg[sbase + t] * sm_col[t];
            }
            if (m != h)
                acc -= ss[sbase + m] * q1T_in[hbase + m]
                     + sc[sbase + m] * sm_row[m]
                     + sg[sbase + m] * sm_col[m];
            f = acc;
        }
        float q = se[idx] + f;
        if (FINAL) {
            out[(long)idx * 2 + 0] = 1.f / (1.f + expf(q));
            out[(long)idx * 2 + 1] = 1.f / (1.f + expf(-q));
        } else {
            float q1v = 1.f / (1.f + expf(-q));
            int ob = (parity ^ 1) & 1;
            g_q1 [ob][idx] = q1v;
            g_q1T[ob][(b * S + h) * S + m] = q1v;
        }
    }
}

extern "C" void kernel_launch(void* const* d_in, const int* in_sizes, int n_in,
                              void* d_out, int out_size)
{
    const float* se = (const float*)d_in[0];
    const float* ss = (const float*)d_in[1];
    const float* sc = (const float*)d_in[2];
    const float* sg = (const float*)d_in[3];
    const int* mask = (const int*)d_in[4];
    float* out = (float*)d_out;

    int BSS = in_sizes[0];                  // B*S*S
    int S = in_sizes[1] / BSS;              // (B*S^3)/(B*S^2)
    int B = BSS / (S * S);

    excl_build_kernel<<<B * S, (S + 31) & ~31>>>(mask, S);

    int ntile = (S + 31) / 32;
    dim3 grid(B * S * ntile);
    size_t smem = 2 * (size_t)S * sizeof(float);

    if (S == 160) {
        // iter 1: fp32 sum (Q1=0.5) + fp16 conversion of scores -> buf 0
        mfvi_iter0_conv<160><<<grid, 256>>>(se, ss, sc, sg, mask, 0);
        // iter 2: fp16 streams, read buf 0, write buf 1
        mfvi_iter_h<0, 160><<<grid, 128, smem>>>(se, mask, out, 0);
        // iter 3: fp16 streams, read buf 1, write output
        mfvi_iter_h<1, 160><<<grid, 128, smem>>>(se, mask, out, 1);
    } else {
        mfvi_iter0_gen<<<grid, 256>>>(se, ss, sc, sg, mask, S, 0);
        mfvi_fallback<0><<<grid, 256, smem>>>(se, ss, sc, sg, mask, out, S, 0);
        mfvi_fallback<1><<<grid, 256, smem>>>(se, ss, sc, sg, mask, out, S, 1);
    }
}